// round 14
// baseline (speedup 1.0000x reference)
#include <cuda_runtime.h>
#include <cuda_bf16.h>
#include <cstdint>
#include <math.h>

#define NN   10000
#define EE   320000
#define DIN  256
#define HIDN 128
#define DALL 256
#define MM   100000
#define PP   15000
#define NB   79                    // ceil(NN/128)
#define NTILES ((NB*(NB+1))/2)     // 3160 upper-tri tiles
#define K3   768                   // 3-term bf16 split K for sup GEMM
#define PREP_T   (2*NN*32 + 2*DIN*HIDN)      // 705536 prep threads
#define PREP_B   ((PREP_T + 255)/256)        // 2756
#define CNT_B    (2*EE/256)                  // 2500
#define FRONT_B  (CNT_B + PREP_B)
#define SUP_B    (2*NB)                      // 158
#define MID_B    (SUP_B + CNT_B)
#define GR_B     (MM/32)                     // 3125 real blocks (32 pairs each)
#define GL_B     ((PP+31)/32)                // 469 lc blocks
#define GN_B     ((NN+31)/32)                // 313 negs blocks
#define GATHER_B (GR_B + GL_B)

// ---------------- static device scratch (no allocations allowed) ------------
__device__ float  g_sup[2][NN*HIDN];
__device__ int    g_off[2][NN+1];        // zero-init by loader; re-zeroed by k_final
__device__ int    g_cur[2][NN];
__device__ int2   g_edge[2][EE];         // {src*512 (byte off), val bits}
__device__ float  g_negs[NN];
__device__ double g_acc[3];              // [0]=real [1]=pseudo [2]=lc ; re-zeroed by k_final
__device__ __align__(16) signed char    g_xq8[NN*256];     // int8 quantized xn, 2.56 MB
__device__ __align__(16) __nv_bfloat16  g_xnb[NN*DALL];    // bf16 xn, 5.12 MB
__device__ __align__(16) __nv_bfloat16  g_x3[2*NN*K3];     // (xh,xl,xh) triples
__device__ __align__(16) __nv_bfloat16  g_w3[2*HIDN*K3];   // (Wh,Wh,Wl) triples

// ---------------- helpers ----------------------------------------------------
__device__ __forceinline__ int tri_off(int b) { return b*NB - (b*(b-1))/2; }

__device__ __forceinline__ void cpa16(uint32_t smem_dst, const void* gsrc, int valid) {
    asm volatile("cp.async.cg.shared.global [%0], [%1], 16, %2;\n"
                 :: "r"(smem_dst), "l"(gsrc), "r"(valid ? 16 : 0));
}

__device__ __forceinline__ float dot8bf(uint4 a, uint4 b) {
    const __nv_bfloat162* pa = (const __nv_bfloat162*)&a;
    const __nv_bfloat162* pb = (const __nv_bfloat162*)&b;
    float s = 0.f;
#pragma unroll
    for (int i = 0; i < 4; i++) {
        float2 fa = __bfloat1622float2(pa[i]);
        float2 fb = __bfloat1622float2(pb[i]);
        s = fmaf(fa.x, fb.x, s);
        s = fmaf(fa.y, fb.y, s);
    }
    return s;
}

// ================= FRONT: edge counting ∥ bf16 split prep =====================
__global__ __launch_bounds__(256)
void k_front(const int* __restrict__ d0, const int* __restrict__ d1,
             const float* __restrict__ x0, const float* __restrict__ x1,
             const float* __restrict__ W0, const float* __restrict__ W1) {
    int b = blockIdx.x;
    if (b < CNT_B) {
        int i = b*256 + threadIdx.x;
        if (i < EE)            atomicAdd(&g_off[0][d0[i]+1], 1);
        else if (i < 2*EE)     atomicAdd(&g_off[1][d1[i-EE]+1], 1);
        return;
    }
    int i = (b - CNT_B)*256 + threadIdx.x;
    if (i < 2*NN*32) {
        int g   = i / (NN*32);
        int rr  = i % (NN*32);
        int n   = rr >> 5;
        int k0  = (rr & 31) * 8;
        const float* src = (g ? x1 : x0) + (size_t)n*DIN + k0;
        float4 v0 = *(const float4*)(src);
        float4 v1 = *(const float4*)(src + 4);
        float xv[8] = {v0.x,v0.y,v0.z,v0.w,v1.x,v1.y,v1.z,v1.w};
        __nv_bfloat16 o[24];
#pragma unroll
        for (int j = 0; j < 8; j++) {
            __nv_bfloat16 h = __float2bfloat16_rn(xv[j]);
            __nv_bfloat16 l = __float2bfloat16_rn(xv[j] - __bfloat162float(h));
            o[3*j] = h; o[3*j+1] = l; o[3*j+2] = h;
        }
        __nv_bfloat16* dst = g_x3 + ((size_t)g*NN + n)*K3 + k0*3;
        ((uint4*)dst)[0] = ((uint4*)o)[0];
        ((uint4*)dst)[1] = ((uint4*)o)[1];
        ((uint4*)dst)[2] = ((uint4*)o)[2];
    } else if (i < PREP_T) {
        int j = i - 2*NN*32;
        int g = j >> 15;
        int rem = j & 32767;
        int k = rem >> 7;
        int n = rem & 127;
        float wv = (g ? W1 : W0)[(size_t)k*HIDN + n];
        __nv_bfloat16 h = __float2bfloat16_rn(wv);
        __nv_bfloat16 l = __float2bfloat16_rn(wv - __bfloat162float(h));
        size_t wb = ((size_t)g*HIDN + n)*K3 + 3*k;
        g_w3[wb] = h; g_w3[wb+1] = h; g_w3[wb+2] = l;
    }
}

// ---------------- CSR build: parallel scan (1 block, 512 threads) ------------
__global__ void k_scan() {
    __shared__ int wsum[17];
    int tid = threadIdx.x, lane = tid & 31, w = tid >> 5;
    const int TOT = NN+1;
    const int CH  = (TOT + 511)/512;   // 20
    for (int g = 0; g < 2; g++) {
        int s = tid*CH, e = min(s+CH, TOT);
        int sum = 0;
        for (int i = s; i < e; i++) sum += g_off[g][i];
        int v = sum;
#pragma unroll
        for (int o = 1; o < 32; o <<= 1) {
            int t = __shfl_up_sync(0xffffffffu, v, o);
            if (lane >= o) v += t;
        }
        if (lane == 31) wsum[w+1] = v;
        __syncthreads();
        if (w == 0) {
            int x = (lane < 16) ? wsum[lane+1] : 0;
#pragma unroll
            for (int o = 1; o < 16; o <<= 1) {
                int t = __shfl_up_sync(0xffffffffu, x, o);
                if (lane >= o) x += t;
            }
            if (lane < 16) wsum[lane+1] = x;
            if (lane == 0) wsum[0] = 0;
        }
        __syncthreads();
        int run = v - sum + wsum[w];
        for (int i = s; i < e; i++) {
            run += g_off[g][i];
            g_off[g][i] = run;
            if (i < NN) g_cur[g][i] = run;
        }
        __syncthreads();
    }
}

// ================= MID: sup tensor GEMM ∥ CSR fill ============================
__global__ __launch_bounds__(256)
void k_mid(const int* __restrict__ s0, const int* __restrict__ d0,
           const float* __restrict__ v0,
           const int* __restrict__ s1, const int* __restrict__ d1,
           const float* __restrict__ v1,
           const float* __restrict__ b0, const float* __restrict__ b1) {
    __shared__ __align__(16) char As[16384];
    __shared__ __align__(16) char Bs[16384];

    int b = blockIdx.x;
    if (b >= SUP_B) {
        int i = (b - SUP_B)*256 + threadIdx.x;
        if (i < EE) {
            int p = atomicAdd(&g_cur[0][d0[i]], 1);
            g_edge[0][p] = make_int2(s0[i]*512, __float_as_int(v0[i]));
        } else if (i < 2*EE) {
            int j = i - EE;
            int p = atomicAdd(&g_cur[1][d1[j]], 1);
            g_edge[1][p] = make_int2(s1[j]*512, __float_as_int(v1[j]));
        }
        return;
    }

    // sup GEMM role: sup = x @ W + b (bf16 mma, 3-term split, K=768)
    int g   = b / NB;
    int rb  = (b % NB) * 128;
    int tid = threadIdx.x;
    int lane = tid & 31;
    int wid  = tid >> 5;
    int wm   = (wid >> 2) * 64;
    int wn   = (wid & 3)  * 32;

    const float* bias = g ? b1 : b0;
    float* sup = g_sup[g];

    float acc[4][4][4];
#pragma unroll
    for (int a = 0; a < 4; a++)
#pragma unroll
        for (int bq = 0; bq < 4; bq++)
#pragma unroll
            for (int c = 0; c < 4; c++) acc[a][bq][c] = 0.f;

    const char* xb = (const char*)(g_x3 + (size_t)g*NN*K3);
    const char* wb = (const char*)(g_w3 + (size_t)g*HIDN*K3);

    for (int kc = 0; kc < 12; kc++) {
#pragma unroll
        for (int p = 0; p < 4; p++) {
            int idx = p*256 + tid;
            int row = idx >> 3;
            int cb  = (idx & 7) * 16;
            int sw  = row*128 + (cb ^ ((row & 7) * 16));
            int ga  = rb + row;
            uint4 va = make_uint4(0u,0u,0u,0u);
            if (ga < NN) va = *(const uint4*)(xb + (size_t)ga*1536 + kc*128 + cb);
            uint4 vb = *(const uint4*)(wb + (size_t)row*1536 + kc*128 + cb);
            *(uint4*)(As + sw) = va;
            *(uint4*)(Bs + sw) = vb;
        }
        __syncthreads();
#pragma unroll
        for (int ks = 0; ks < 4; ks++) {
            uint32_t afr[4][4];
            uint32_t bfr[2][4];
            int cbk = ks*32 + (lane >> 4)*16;
#pragma unroll
            for (int mb = 0; mb < 4; mb++) {
                int row = wm + mb*16 + (lane & 15);
                uint32_t sa = (uint32_t)__cvta_generic_to_shared(
                                  As + row*128 + (cbk ^ ((row & 7) * 16)));
                asm volatile("ldmatrix.sync.aligned.m8n8.x4.shared.b16 {%0,%1,%2,%3}, [%4];"
                    : "=r"(afr[mb][0]), "=r"(afr[mb][1]), "=r"(afr[mb][2]), "=r"(afr[mb][3])
                    : "r"(sa));
            }
#pragma unroll
            for (int nb2 = 0; nb2 < 2; nb2++) {
                int row = wn + nb2*16 + (lane & 15);
                uint32_t sb = (uint32_t)__cvta_generic_to_shared(
                                  Bs + row*128 + (cbk ^ ((row & 7) * 16)));
                asm volatile("ldmatrix.sync.aligned.m8n8.x4.shared.b16 {%0,%1,%2,%3}, [%4];"
                    : "=r"(bfr[nb2][0]), "=r"(bfr[nb2][1]), "=r"(bfr[nb2][2]), "=r"(bfr[nb2][3])
                    : "r"(sb));
            }
#pragma unroll
            for (int mb = 0; mb < 4; mb++)
#pragma unroll
                for (int nb = 0; nb < 4; nb++) {
                    int h = nb >> 1, o = nb & 1;
                    asm volatile(
                        "mma.sync.aligned.m16n8k16.row.col.f32.bf16.bf16.f32 "
                        "{%0,%1,%2,%3}, {%4,%5,%6,%7}, {%8,%9}, {%0,%1,%2,%3};"
                        : "+f"(acc[mb][nb][0]), "+f"(acc[mb][nb][1]),
                          "+f"(acc[mb][nb][2]), "+f"(acc[mb][nb][3])
                        : "r"(afr[mb][0]), "r"(afr[mb][1]), "r"(afr[mb][2]), "r"(afr[mb][3]),
                          "r"(bfr[h][o]),  "r"(bfr[h][o+2]));
                }
        }
        __syncthreads();
    }

#pragma unroll
    for (int nb = 0; nb < 4; nb++) {
        int col = wn + nb*8 + (lane & 3)*2;
        float bc0 = bias[col], bc1 = bias[col+1];
#pragma unroll
        for (int mb = 0; mb < 4; mb++) {
            int r = wm + mb*16 + (lane >> 2);
            int gr0 = rb + r, gr1 = rb + r + 8;
            if (gr0 < NN) {
                float2 o = make_float2(acc[mb][nb][0] + bc0, acc[mb][nb][1] + bc1);
                *(float2*)(sup + (size_t)gr0*HIDN + col) = o;
            }
            if (gr1 < NN) {
                float2 o = make_float2(acc[mb][nb][2] + bc0, acc[mb][nb][3] + bc1);
                *(float2*)(sup + (size_t)gr1*HIDN + col) = o;
            }
        }
    }
}

// ------- aggregate + l2norm -> x_all + fused int8/bf16 casts (warp-per-edge) --
__global__ __launch_bounds__(128)
void k_agg(float* __restrict__ out) {
    int n   = blockIdx.x;
    int g   = blockIdx.y;
    int tid = threadIdx.x;
    int lane = tid & 31;
    int w    = tid >> 5;
    const char* supb = (const char*)g_sup[g] + lane*16;

    float4 a4 = make_float4(0.f, 0.f, 0.f, 0.f);
    int s0 = g_off[g][n], s1 = g_off[g][n+1];
    const int2* edges = g_edge[g];
#pragma unroll 4
    for (int e = s0 + w; e < s1; e += 4) {
        int2 rec = edges[e];
        float4 v = *(const float4*)(supb + rec.x);
        float val = __int_as_float(rec.y);
        a4.x = fmaf(v.x, val, a4.x);
        a4.y = fmaf(v.y, val, a4.y);
        a4.z = fmaf(v.z, val, a4.z);
        a4.w = fmaf(v.w, val, a4.w);
    }
    __shared__ float part[4][128];
    *(float4*)&part[w][lane*4] = a4;
    __syncthreads();
    float acc = part[0][tid] + part[1][tid] + part[2][tid] + part[3][tid];

    float sq = acc*acc;
#pragma unroll
    for (int o = 16; o; o >>= 1) sq += __shfl_xor_sync(0xffffffffu, sq, o);
    __shared__ float wsum[4];
    if (lane == 0) wsum[w] = sq;
    __syncthreads();
    float tot = wsum[0] + wsum[1] + wsum[2] + wsum[3];
    float v = acc / sqrtf(tot);
    out[(size_t)n*DALL + g*HIDN + tid] = v;

    float xs = v * 0.70710678118654752440f;
    int q = __float2int_rn(xs * 127.0f);
    q = max(-127, min(127, q));
    g_xq8[(size_t)n*256 + g*128 + tid] = (signed char)q;
    g_xnb[(size_t)n*DALL + g*128 + tid] = __float2bfloat16_rn(xs);
}

// ---------------- neg_s precompute (bf16, lean) --------------------------------
__global__ __launch_bounds__(256)
void k_negs(const int* __restrict__ negrow) {
    int lane = threadIdx.x & 31;
    int wid  = threadIdx.x >> 5;
#pragma unroll
    for (int pq = 0; pq < 4; pq++) {
        int row = blockIdx.x*32 + wid*4 + pq;
        if (row >= NN) break;
        int jn = negrow[row];
        uint4 a = ((const uint4*)(g_xnb + (size_t)row*DALL))[lane];
        uint4 b = ((const uint4*)(g_xnb + (size_t)jn*DALL))[lane];
        float s = dot8bf(a, b);
#pragma unroll
        for (int o = 16; o; o >>= 1) s += __shfl_xor_sync(0xffffffffu, s, o);
        if (lane == 0) g_negs[row] = s;   // bf16 xn rows are unit-norm
    }
}

// ========== GATHER: loss_real + lc (bf16 rows, high occupancy) ================
__global__ __launch_bounds__(256)
void k_gather(const int* __restrict__ ts, const int* __restrict__ negidx,
              const int* __restrict__ na, const int* __restrict__ nbv,
              const int* __restrict__ nl) {
    __shared__ float wr[8];
    int b    = blockIdx.x;
    int tid  = threadIdx.x;
    int lane = tid & 31;
    int wid  = tid >> 5;

    if (b < GR_B) {
        // -------- REAL role: 32 pairs/block, 4 per warp --------
        float term = 0.f;
#pragma unroll
        for (int pq = 0; pq < 4; pq++) {
            int pid = b*32 + wid*4 + pq;
            int t0 = ts[2*pid], t1 = ts[2*pid+1], tn = negidx[pid];
            uint4 r = ((const uint4*)(g_xnb + (size_t)t0*DALL))[lane];
            uint4 e = ((const uint4*)(g_xnb + (size_t)t1*DALL))[lane];
            uint4 n = ((const uint4*)(g_xnb + (size_t)tn*DALL))[lane];
            float ps = dot8bf(r, e);
            float ns = dot8bf(r, n);
#pragma unroll
            for (int o = 16; o; o >>= 1) {
                ps += __shfl_xor_sync(0xffffffffu, ps, o);
                ns += __shfl_xor_sync(0xffffffffu, ns, o);
            }
            if (lane == 0) {
                float u = (ps - 0.1f) * (1.0f/0.9f);
                term += (u*u) * log1pf(expf(ns - ps));
            }
        }
        if (lane == 0) wr[wid] = term;
        __syncthreads();
        if (tid == 0) {
            double s = 0;
#pragma unroll
            for (int q = 0; q < 8; q++) s += (double)wr[q];
            atomicAdd(&g_acc[0], s);
        }
    } else {
        // -------- LC role: 32 pairs/block, 4 per warp --------
        int b2 = b - GR_B;
        float term = 0.f;
#pragma unroll
        for (int pq = 0; pq < 4; pq++) {
            int pid = b2*32 + wid*4 + pq;
            if (pid >= PP) break;
            int ia = na[pid], ib = nbv[pid];
            uint4 a  = ((const uint4*)(g_xnb + (size_t)ia*DALL))[lane];
            uint4 bb = ((const uint4*)(g_xnb + (size_t)ib*DALL))[lane];
            float s = dot8bf(a, bb);
#pragma unroll
            for (int o = 16; o; o >>= 1) s += __shfl_xor_sync(0xffffffffu, s, o);
            if (lane == 0) {
                float z   = s * 2.0f;                 // sim / TAU0
                float ls  = (z >= 0.f) ? -log1pf(expf(-z)) : (z - log1pf(expf(z)));
                int   L   = nl[pid];
                term += ldexpf(1.0f, -(L+1)) * ls;    // 0.5^(L+1)
            }
        }
        if (lane == 0) wr[wid] = term;
        __syncthreads();
        if (tid == 0) {
            double s = 0;
#pragma unroll
            for (int q = 0; q < 8; q++) s += (double)wr[q];
            atomicAdd(&g_acc[2], s);
        }
    }
}

// ============ PSEUDO: int8 IMMA screen-GEMM over triu tiles ===================
__global__ __launch_bounds__(256, 2)
void k_pseudo(const float* __restrict__ xall) {
    __shared__ __align__(128) char As[2][16384];
    __shared__ __align__(128) char Bs[2][16384];
    __shared__ double wred[8];

    int tid  = threadIdx.x;
    int lane = tid & 31;
    int wid  = tid >> 5;

    int t = blockIdx.x;
    float ff = (float)NB + 0.5f;
    int bi = (int)(ff - sqrtf(ff*ff - 2.0f*t));
    if (bi < 0) bi = 0; if (bi >= NB) bi = NB-1;
    while (bi > 0 && tri_off(bi) > t) bi--;
    while (tri_off(bi+1) <= t) bi++;
    int bj = bi + (t - tri_off(bi));
    int rA = bi * 128, rB = bj * 128;

    int wm = (wid >> 2) * 64;
    int wn = (wid & 3)  * 32;

    int acc[4][4][4];
#pragma unroll
    for (int a = 0; a < 4; a++)
#pragma unroll
        for (int bq = 0; bq < 4; bq++)
#pragma unroll
            for (int c = 0; c < 4; c++) acc[a][bq][c] = 0;

    const char* xbytes = (const char*)g_xq8;   // 256 B per row

    int r0 = tid >> 3;
    int cb = (tid & 7) * 16;

#pragma unroll
    for (int c = 0; c < 2; c++) {
        uint32_t a0 = (uint32_t)__cvta_generic_to_shared(As[c]);
        uint32_t b0 = (uint32_t)__cvta_generic_to_shared(Bs[c]);
#pragma unroll
        for (int p = 0; p < 4; p++) {
            int row = r0 + p*32;
            int sw  = row*128 + (cb ^ ((row & 7) * 16));
            int ga = rA + row, gb = rB + row;
            cpa16(a0 + sw, xbytes + (size_t)min(ga, NN-1)*256 + c*128 + cb, ga < NN);
            cpa16(b0 + sw, xbytes + (size_t)min(gb, NN-1)*256 + c*128 + cb, gb < NN);
        }
        asm volatile("cp.async.commit_group;\n");
    }

#pragma unroll
    for (int c = 0; c < 2; c++) {
        if (c == 0) asm volatile("cp.async.wait_group 1;\n");
        else        asm volatile("cp.async.wait_group 0;\n");
        __syncthreads();
        const char* Ab = As[c];
        const char* Bb = Bs[c];
#pragma unroll
        for (int ks = 0; ks < 4; ks++) {
            uint32_t afr[4][4];
            uint32_t bfr[2][4];
            int cbk = ks*32 + (lane >> 4)*16;
#pragma unroll
            for (int mb = 0; mb < 4; mb++) {
                int row = wm + mb*16 + (lane & 15);
                uint32_t sa = (uint32_t)__cvta_generic_to_shared(
                                  Ab + row*128 + (cbk ^ ((row & 7) * 16)));
                asm volatile("ldmatrix.sync.aligned.m8n8.x4.shared.b16 {%0,%1,%2,%3}, [%4];"
                    : "=r"(afr[mb][0]), "=r"(afr[mb][1]), "=r"(afr[mb][2]), "=r"(afr[mb][3])
                    : "r"(sa));
            }
#pragma unroll
            for (int nb2 = 0; nb2 < 2; nb2++) {
                int row = wn + nb2*16 + (lane & 15);
                uint32_t sb = (uint32_t)__cvta_generic_to_shared(
                                  Bb + row*128 + (cbk ^ ((row & 7) * 16)));
                asm volatile("ldmatrix.sync.aligned.m8n8.x4.shared.b16 {%0,%1,%2,%3}, [%4];"
                    : "=r"(bfr[nb2][0]), "=r"(bfr[nb2][1]), "=r"(bfr[nb2][2]), "=r"(bfr[nb2][3])
                    : "r"(sb));
            }
#pragma unroll
            for (int mb = 0; mb < 4; mb++)
#pragma unroll
                for (int nb = 0; nb < 4; nb++) {
                    int h = nb >> 1, o = nb & 1;
                    asm volatile(
                        "mma.sync.aligned.m16n8k32.row.col.satfinite.s32.s8.s8.s32 "
                        "{%0,%1,%2,%3}, {%4,%5,%6,%7}, {%8,%9}, {%0,%1,%2,%3};"
                        : "+r"(acc[mb][nb][0]), "+r"(acc[mb][nb][1]),
                          "+r"(acc[mb][nb][2]), "+r"(acc[mb][nb][3])
                        : "r"(afr[mb][0]), "r"(afr[mb][1]), "r"(afr[mb][2]), "r"(afr[mb][3]),
                          "r"(bfr[h][o]),  "r"(bfr[h][o+2]));
                }
        }
        __syncthreads();
    }

    // epilogue: screen at 0.90 (int8 quantization margin), exact fp32
    // recompute for rare candidates; neg_s from precomputed table.
    const float qscale = 1.0f / 16129.0f;   // 1/127^2
    float lsum = 0.f;
#pragma unroll
    for (int mb = 0; mb < 4; mb++) {
        int rr0 = rA + wm + mb*16 + (lane >> 2);
#pragma unroll
        for (int nb = 0; nb < 4; nb++) {
            int c0 = rB + wn + nb*8 + (lane & 3)*2;
#pragma unroll
            for (int e = 0; e < 4; e++) {
                int gi = rr0 + (e >= 2 ? 8 : 0);
                int gj = c0 + (e & 1);
                float s = (float)acc[mb][nb][e] * qscale;
                if (gj > gi && gj < NN && gi < NN && s > 0.90f) {
                    const float4* av = (const float4*)(xall + (size_t)gi*DALL);
                    const float4* bv = (const float4*)(xall + (size_t)gj*DALL);
                    float d = 0.f;
#pragma unroll 4
                    for (int q = 0; q < 64; q++) {
                        float4 x = av[q], y = bv[q];
                        d += x.x*y.x + x.y*y.y + x.z*y.z + x.w*y.w;
                    }
                    float se = 0.5f * d;
                    if (se > 0.95f) {
                        float u = (se - 0.1f) * (1.0f/0.9f);
                        lsum += (u*u) * log1pf(expf(g_negs[gi] - se));
                    }
                }
            }
        }
    }
    float v = lsum;
#pragma unroll
    for (int o = 16; o; o >>= 1) v += __shfl_xor_sync(0xffffffffu, v, o);
    if (lane == 0) wred[wid] = (double)v;
    __syncthreads();
    if (tid == 0) {
        double s = 0;
#pragma unroll
        for (int q = 0; q < 8; q++) s += wred[q];
        if (s != 0.0) atomicAdd(&g_acc[1], s);
    }
}

// ---------------- finalize + re-zero scratch for next replay ------------------
__global__ void k_final(float* out, int loss_idx) {
    int i = blockIdx.x*blockDim.x + threadIdx.x;
    if (i == 0) {
        double lc   = -g_acc[2] / (double)PP;
        double loss = g_acc[0] + g_acc[1] + 1.0 * lc;   // LAMBDA1 = 1
        out[loss_idx] = (float)loss;
        g_acc[0] = 0.0; g_acc[1] = 0.0; g_acc[2] = 0.0;
    }
    if (i < 2*(NN+1)) ((int*)g_off)[i] = 0;
}

// ---------------- launch (forked streams: gather ∥ pseudo) ---------------------
extern "C" void kernel_launch(void* const* d_in, const int* in_sizes, int n_in,
                              void* d_out, int out_size) {
    const float* x0  = (const float*)d_in[0];
    const float* x1  = (const float*)d_in[1];
    const int*   a0s = (const int*)d_in[2];
    const int*   a0d = (const int*)d_in[3];
    const float* a0v = (const float*)d_in[4];
    const int*   a1s = (const int*)d_in[5];
    const int*   a1d = (const int*)d_in[6];
    const float* a1v = (const float*)d_in[7];
    const int*   ts  = (const int*)d_in[8];
    const int*   ngi = (const int*)d_in[9];
    const int*   ngr = (const int*)d_in[10];
    const int*   na  = (const int*)d_in[11];
    const int*   nb  = (const int*)d_in[12];
    const int*   nl  = (const int*)d_in[13];
    const float* W0  = (const float*)d_in[14];
    const float* b0  = (const float*)d_in[15];
    const float* W1  = (const float*)d_in[16];
    const float* b1  = (const float*)d_in[17];
    float* out = (float*)d_out;

    // created once on the (uncaptured) correctness call; reused by capture
    static cudaStream_t s2 = nullptr;
    static cudaEvent_t  evF = nullptr, evJ = nullptr;
    if (s2 == nullptr) {
        cudaStreamCreateWithFlags(&s2, cudaStreamNonBlocking);
        cudaEventCreateWithFlags(&evF, cudaEventDisableTiming);
        cudaEventCreateWithFlags(&evJ, cudaEventDisableTiming);
    }

    k_front <<<FRONT_B, 256>>>(a0d, a1d, x0, x1, W0, W1);
    k_scan  <<<1, 512>>>();
    k_mid   <<<MID_B, 256>>>(a0s, a0d, a0v, a1s, a1d, a1v, b0, b1);
    k_agg   <<<dim3(NN,2), 128>>>(out);         // 4th launch -> ncu capture slot
    k_negs  <<<GN_B, 256>>>(ngr);

    cudaEventRecord(evF, 0);
    cudaStreamWaitEvent(s2, evF, 0);
    k_pseudo<<<NTILES, 256, 0, s2>>>(out);      // branch: tensor-bound
    cudaEventRecord(evJ, s2);

    k_gather<<<GATHER_B, 256>>>(ts, ngi, na, nb, nl);  // main: latency-bound
    cudaStreamWaitEvent(0, evJ, 0);
    k_final <<<(2*(NN+1)+255)/256, 256>>>(out, out_size - 1);
}

// round 15
// speedup vs baseline: 1.9150x; 1.9150x over previous
#include <cuda_runtime.h>
#include <cuda_bf16.h>
#include <cuda_fp8.h>
#include <cstdint>
#include <math.h>

#define NN   10000
#define EE   320000
#define DIN  256
#define HIDN 128
#define DALL 256
#define MM   100000
#define PP   15000
#define NB   79                    // ceil(NN/128)
#define NTILES ((NB*(NB+1))/2)     // 3160 upper-tri tiles
#define K3   768                   // 3-term bf16 split K for sup GEMM
#define PREP_T   (2*NN*32 + 2*DIN*HIDN)      // 705536 prep threads
#define PREP_B   ((PREP_T + 255)/256)        // 2756
#define CNT_B    (2*EE/256)                  // 2500
#define FRONT_B  (CNT_B + PREP_B)
#define GR_B     (MM/32)                     // 3125 real blocks (32 pairs each)
#define GL_B     ((PP+31)/32)                // 469 lc blocks
#define GN_B     ((NN+31)/32)                // 313 negs blocks
#define GATHER_B (GR_B + GL_B)

// ---------------- static device scratch (no allocations allowed) ------------
__device__ float  g_sup[2][NN*HIDN];
__device__ int    g_off[2][NN+1];        // zero-init by loader; re-zeroed by k_final
__device__ int    g_cur[2][NN];
__device__ int2   g_edge[2][EE];         // {src*512 (byte off), val bits}
__device__ float  g_negs[NN];
__device__ double g_acc[3];              // [0]=real [1]=pseudo [2]=lc ; re-zeroed by k_final
__device__ __align__(16) unsigned char  g_xcat8[NN*256];   // e4m3 xn, 2.56 MB
__device__ __align__(16) __nv_bfloat16  g_xnb[NN*DALL];    // bf16 xn, 5.12 MB
__device__ __align__(16) __nv_bfloat16  g_x3[2*NN*K3];     // (xh,xl,xh) triples
__device__ __align__(16) __nv_bfloat16  g_w3[2*HIDN*K3];   // (Wh,Wh,Wl) triples

// ---------------- helpers ----------------------------------------------------
__device__ __forceinline__ int tri_off(int b) { return b*NB - (b*(b-1))/2; }

__device__ __forceinline__ void cpa16(uint32_t smem_dst, const void* gsrc, int valid) {
    asm volatile("cp.async.cg.shared.global [%0], [%1], 16, %2;\n"
                 :: "r"(smem_dst), "l"(gsrc), "r"(valid ? 16 : 0));
}

__device__ __forceinline__ float dot8bf(uint4 a, uint4 b) {
    const __nv_bfloat162* pa = (const __nv_bfloat162*)&a;
    const __nv_bfloat162* pb = (const __nv_bfloat162*)&b;
    float s = 0.f;
#pragma unroll
    for (int i = 0; i < 4; i++) {
        float2 fa = __bfloat1622float2(pa[i]);
        float2 fb = __bfloat1622float2(pb[i]);
        s = fmaf(fa.x, fb.x, s);
        s = fmaf(fa.y, fb.y, s);
    }
    return s;
}

// ================= FRONT: edge counting ∥ bf16 split prep =====================
__global__ __launch_bounds__(256)
void k_front(const int* __restrict__ d0, const int* __restrict__ d1,
             const float* __restrict__ x0, const float* __restrict__ x1,
             const float* __restrict__ W0, const float* __restrict__ W1) {
    int b = blockIdx.x;
    if (b < CNT_B) {
        int i = b*256 + threadIdx.x;
        if (i < EE)            atomicAdd(&g_off[0][d0[i]+1], 1);
        else if (i < 2*EE)     atomicAdd(&g_off[1][d1[i-EE]+1], 1);
        return;
    }
    int i = (b - CNT_B)*256 + threadIdx.x;
    if (i < 2*NN*32) {
        int g   = i / (NN*32);
        int rr  = i % (NN*32);
        int n   = rr >> 5;
        int k0  = (rr & 31) * 8;
        const float* src = (g ? x1 : x0) + (size_t)n*DIN + k0;
        float4 v0 = *(const float4*)(src);
        float4 v1 = *(const float4*)(src + 4);
        float xv[8] = {v0.x,v0.y,v0.z,v0.w,v1.x,v1.y,v1.z,v1.w};
        __nv_bfloat16 o[24];
#pragma unroll
        for (int j = 0; j < 8; j++) {
            __nv_bfloat16 h = __float2bfloat16_rn(xv[j]);
            __nv_bfloat16 l = __float2bfloat16_rn(xv[j] - __bfloat162float(h));
            o[3*j] = h; o[3*j+1] = l; o[3*j+2] = h;
        }
        __nv_bfloat16* dst = g_x3 + ((size_t)g*NN + n)*K3 + k0*3;
        ((uint4*)dst)[0] = ((uint4*)o)[0];
        ((uint4*)dst)[1] = ((uint4*)o)[1];
        ((uint4*)dst)[2] = ((uint4*)o)[2];
    } else if (i < PREP_T) {
        int j = i - 2*NN*32;
        int g = j >> 15;
        int rem = j & 32767;
        int k = rem >> 7;
        int n = rem & 127;
        float wv = (g ? W1 : W0)[(size_t)k*HIDN + n];
        __nv_bfloat16 h = __float2bfloat16_rn(wv);
        __nv_bfloat16 l = __float2bfloat16_rn(wv - __bfloat162float(h));
        size_t wb = ((size_t)g*HIDN + n)*K3 + 3*k;
        g_w3[wb] = h; g_w3[wb+1] = h; g_w3[wb+2] = l;
    }
}

// ---------------- CSR build: parallel scan (1 block, 512 threads) ------------
__global__ void k_scan() {
    __shared__ int wsum[17];
    int tid = threadIdx.x, lane = tid & 31, w = tid >> 5;
    const int TOT = NN+1;
    const int CH  = (TOT + 511)/512;   // 20
    for (int g = 0; g < 2; g++) {
        int s = tid*CH, e = min(s+CH, TOT);
        int sum = 0;
        for (int i = s; i < e; i++) sum += g_off[g][i];
        int v = sum;
#pragma unroll
        for (int o = 1; o < 32; o <<= 1) {
            int t = __shfl_up_sync(0xffffffffu, v, o);
            if (lane >= o) v += t;
        }
        if (lane == 31) wsum[w+1] = v;
        __syncthreads();
        if (w == 0) {
            int x = (lane < 16) ? wsum[lane+1] : 0;
#pragma unroll
            for (int o = 1; o < 16; o <<= 1) {
                int t = __shfl_up_sync(0xffffffffu, x, o);
                if (lane >= o) x += t;
            }
            if (lane < 16) wsum[lane+1] = x;
            if (lane == 0) wsum[0] = 0;
        }
        __syncthreads();
        int run = v - sum + wsum[w];
        for (int i = s; i < e; i++) {
            run += g_off[g][i];
            g_off[g][i] = run;
            if (i < NN) g_cur[g][i] = run;
        }
        __syncthreads();
    }
}

// ---------------- CSR fill (edge records) -------------------------------------
__global__ __launch_bounds__(256)
void k_fill(const int* __restrict__ s0, const int* __restrict__ d0,
            const float* __restrict__ v0,
            const int* __restrict__ s1, const int* __restrict__ d1,
            const float* __restrict__ v1) {
    int i = blockIdx.x*256 + threadIdx.x;
    if (i < EE) {
        int p = atomicAdd(&g_cur[0][d0[i]], 1);
        g_edge[0][p] = make_int2(s0[i]*512, __float_as_int(v0[i]));
    } else if (i < 2*EE) {
        int j = i - EE;
        int p = atomicAdd(&g_cur[1][d1[j]], 1);
        g_edge[1][p] = make_int2(s1[j]*512, __float_as_int(v1[j]));
    }
}

// ---------------- sup = x @ W + b (bf16 mma, 3-term split, K=768) -------------
__global__ __launch_bounds__(256)
void k_sup(const float* __restrict__ b0, const float* __restrict__ b1) {
    __shared__ __align__(16) char As[16384];
    __shared__ __align__(16) char Bs[16384];

    int g   = blockIdx.z;
    int rb  = blockIdx.x * 128;
    int tid = threadIdx.x;
    int lane = tid & 31;
    int wid  = tid >> 5;
    int wm   = (wid >> 2) * 64;
    int wn   = (wid & 3)  * 32;

    const float* bias = g ? b1 : b0;
    float* sup = g_sup[g];

    float acc[4][4][4];
#pragma unroll
    for (int a = 0; a < 4; a++)
#pragma unroll
        for (int bq = 0; bq < 4; bq++)
#pragma unroll
            for (int c = 0; c < 4; c++) acc[a][bq][c] = 0.f;

    const char* xb = (const char*)(g_x3 + (size_t)g*NN*K3);
    const char* wb = (const char*)(g_w3 + (size_t)g*HIDN*K3);

    for (int kc = 0; kc < 12; kc++) {
#pragma unroll
        for (int p = 0; p < 4; p++) {
            int idx = p*256 + tid;
            int row = idx >> 3;
            int cb  = (idx & 7) * 16;
            int sw  = row*128 + (cb ^ ((row & 7) * 16));
            int ga  = rb + row;
            uint4 va = make_uint4(0u,0u,0u,0u);
            if (ga < NN) va = *(const uint4*)(xb + (size_t)ga*1536 + kc*128 + cb);
            uint4 vb = *(const uint4*)(wb + (size_t)row*1536 + kc*128 + cb);
            *(uint4*)(As + sw) = va;
            *(uint4*)(Bs + sw) = vb;
        }
        __syncthreads();
#pragma unroll
        for (int ks = 0; ks < 4; ks++) {
            uint32_t afr[4][4];
            uint32_t bfr[2][4];
            int cbk = ks*32 + (lane >> 4)*16;
#pragma unroll
            for (int mb = 0; mb < 4; mb++) {
                int row = wm + mb*16 + (lane & 15);
                uint32_t sa = (uint32_t)__cvta_generic_to_shared(
                                  As + row*128 + (cbk ^ ((row & 7) * 16)));
                asm volatile("ldmatrix.sync.aligned.m8n8.x4.shared.b16 {%0,%1,%2,%3}, [%4];"
                    : "=r"(afr[mb][0]), "=r"(afr[mb][1]), "=r"(afr[mb][2]), "=r"(afr[mb][3])
                    : "r"(sa));
            }
#pragma unroll
            for (int nb2 = 0; nb2 < 2; nb2++) {
                int row = wn + nb2*16 + (lane & 15);
                uint32_t sb = (uint32_t)__cvta_generic_to_shared(
                                  Bs + row*128 + (cbk ^ ((row & 7) * 16)));
                asm volatile("ldmatrix.sync.aligned.m8n8.x4.shared.b16 {%0,%1,%2,%3}, [%4];"
                    : "=r"(bfr[nb2][0]), "=r"(bfr[nb2][1]), "=r"(bfr[nb2][2]), "=r"(bfr[nb2][3])
                    : "r"(sb));
            }
#pragma unroll
            for (int mb = 0; mb < 4; mb++)
#pragma unroll
                for (int nb = 0; nb < 4; nb++) {
                    int h = nb >> 1, o = nb & 1;
                    asm volatile(
                        "mma.sync.aligned.m16n8k16.row.col.f32.bf16.bf16.f32 "
                        "{%0,%1,%2,%3}, {%4,%5,%6,%7}, {%8,%9}, {%0,%1,%2,%3};"
                        : "+f"(acc[mb][nb][0]), "+f"(acc[mb][nb][1]),
                          "+f"(acc[mb][nb][2]), "+f"(acc[mb][nb][3])
                        : "r"(afr[mb][0]), "r"(afr[mb][1]), "r"(afr[mb][2]), "r"(afr[mb][3]),
                          "r"(bfr[h][o]),  "r"(bfr[h][o+2]));
                }
        }
        __syncthreads();
    }

#pragma unroll
    for (int nb = 0; nb < 4; nb++) {
        int col = wn + nb*8 + (lane & 3)*2;
        float bc0 = bias[col], bc1 = bias[col+1];
#pragma unroll
        for (int mb = 0; mb < 4; mb++) {
            int r = wm + mb*16 + (lane >> 2);
            int gr0 = rb + r, gr1 = rb + r + 8;
            if (gr0 < NN) {
                float2 o = make_float2(acc[mb][nb][0] + bc0, acc[mb][nb][1] + bc1);
                *(float2*)(sup + (size_t)gr0*HIDN + col) = o;
            }
            if (gr1 < NN) {
                float2 o = make_float2(acc[mb][nb][2] + bc0, acc[mb][nb][3] + bc1);
                *(float2*)(sup + (size_t)gr1*HIDN + col) = o;
            }
        }
    }
}

// ------- aggregate + l2norm -> x_all + fused fp8/bf16 casts (warp-per-edge) ---
__global__ __launch_bounds__(128)
void k_agg(float* __restrict__ out) {
    int n   = blockIdx.x;
    int g   = blockIdx.y;
    int tid = threadIdx.x;
    int lane = tid & 31;
    int w    = tid >> 5;
    const char* supb = (const char*)g_sup[g] + lane*16;

    float4 a4 = make_float4(0.f, 0.f, 0.f, 0.f);
    int s0 = g_off[g][n], s1 = g_off[g][n+1];
    const int2* edges = g_edge[g];
#pragma unroll 4
    for (int e = s0 + w; e < s1; e += 4) {
        int2 rec = edges[e];
        float4 v = *(const float4*)(supb + rec.x);
        float val = __int_as_float(rec.y);
        a4.x = fmaf(v.x, val, a4.x);
        a4.y = fmaf(v.y, val, a4.y);
        a4.z = fmaf(v.z, val, a4.z);
        a4.w = fmaf(v.w, val, a4.w);
    }
    __shared__ float part[4][128];
    *(float4*)&part[w][lane*4] = a4;
    __syncthreads();
    float acc = part[0][tid] + part[1][tid] + part[2][tid] + part[3][tid];

    float sq = acc*acc;
#pragma unroll
    for (int o = 16; o; o >>= 1) sq += __shfl_xor_sync(0xffffffffu, sq, o);
    __shared__ float wsum[4];
    if (lane == 0) wsum[w] = sq;
    __syncthreads();
    float tot = wsum[0] + wsum[1] + wsum[2] + wsum[3];
    float v = acc / sqrtf(tot);
    out[(size_t)n*DALL + g*HIDN + tid] = v;

    float xs = v * 0.70710678118654752440f;
    g_xcat8[(size_t)n*256 + g*128 + tid] =
        __nv_cvt_float_to_fp8(xs, __NV_SATFINITE, __NV_E4M3);
    g_xnb[(size_t)n*DALL + g*128 + tid] = __float2bfloat16_rn(xs);
}

// ---------------- neg_s precompute (bf16, lean) --------------------------------
__global__ __launch_bounds__(256)
void k_negs(const int* __restrict__ negrow) {
    int lane = threadIdx.x & 31;
    int wid  = threadIdx.x >> 5;
#pragma unroll
    for (int pq = 0; pq < 4; pq++) {
        int row = blockIdx.x*32 + wid*4 + pq;
        if (row >= NN) break;
        int jn = negrow[row];
        uint4 a = ((const uint4*)(g_xnb + (size_t)row*DALL))[lane];
        uint4 b = ((const uint4*)(g_xnb + (size_t)jn*DALL))[lane];
        float s = dot8bf(a, b);
#pragma unroll
        for (int o = 16; o; o >>= 1) s += __shfl_xor_sync(0xffffffffu, s, o);
        if (lane == 0) g_negs[row] = s;   // bf16 xn rows are unit-norm
    }
}

// ========== GATHER: loss_real + lc (bf16 rows, high occupancy) ================
__global__ __launch_bounds__(256)
void k_gather(const int* __restrict__ ts, const int* __restrict__ negidx,
              const int* __restrict__ na, const int* __restrict__ nbv,
              const int* __restrict__ nl) {
    __shared__ float wr[8];
    int b    = blockIdx.x;
    int tid  = threadIdx.x;
    int lane = tid & 31;
    int wid  = tid >> 5;

    if (b < GR_B) {
        // -------- REAL role: 32 pairs/block, 4 per warp --------
        float term = 0.f;
#pragma unroll
        for (int pq = 0; pq < 4; pq++) {
            int pid = b*32 + wid*4 + pq;
            int t0 = ts[2*pid], t1 = ts[2*pid+1], tn = negidx[pid];
            uint4 r = ((const uint4*)(g_xnb + (size_t)t0*DALL))[lane];
            uint4 e = ((const uint4*)(g_xnb + (size_t)t1*DALL))[lane];
            uint4 n = ((const uint4*)(g_xnb + (size_t)tn*DALL))[lane];
            float ps = dot8bf(r, e);
            float ns = dot8bf(r, n);
#pragma unroll
            for (int o = 16; o; o >>= 1) {
                ps += __shfl_xor_sync(0xffffffffu, ps, o);
                ns += __shfl_xor_sync(0xffffffffu, ns, o);
            }
            if (lane == 0) {
                float u = (ps - 0.1f) * (1.0f/0.9f);
                term += (u*u) * log1pf(expf(ns - ps));
            }
        }
        if (lane == 0) wr[wid] = term;
        __syncthreads();
        if (tid == 0) {
            double s = 0;
#pragma unroll
            for (int q = 0; q < 8; q++) s += (double)wr[q];
            atomicAdd(&g_acc[0], s);
        }
    } else {
        // -------- LC role: 32 pairs/block, 4 per warp --------
        int b2 = b - GR_B;
        float term = 0.f;
#pragma unroll
        for (int pq = 0; pq < 4; pq++) {
            int pid = b2*32 + wid*4 + pq;
            if (pid >= PP) break;
            int ia = na[pid], ib = nbv[pid];
            uint4 a  = ((const uint4*)(g_xnb + (size_t)ia*DALL))[lane];
            uint4 bb = ((const uint4*)(g_xnb + (size_t)ib*DALL))[lane];
            float s = dot8bf(a, bb);
#pragma unroll
            for (int o = 16; o; o >>= 1) s += __shfl_xor_sync(0xffffffffu, s, o);
            if (lane == 0) {
                float z   = s * 2.0f;                 // sim / TAU0
                float ls  = (z >= 0.f) ? -log1pf(expf(-z)) : (z - log1pf(expf(z)));
                int   L   = nl[pid];
                term += ldexpf(1.0f, -(L+1)) * ls;    // 0.5^(L+1)
            }
        }
        if (lane == 0) wr[wid] = term;
        __syncthreads();
        if (tid == 0) {
            double s = 0;
#pragma unroll
            for (int q = 0; q < 8; q++) s += (double)wr[q];
            atomicAdd(&g_acc[2], s);
        }
    }
}

// ================= PSEUDO: fp8 screen-GEMM over triu tiles (per-tile) =========
__global__ __launch_bounds__(256, 2)
void k_pseudo(const float* __restrict__ xall) {
    __shared__ __align__(128) char As[2][16384];
    __shared__ __align__(128) char Bs[2][16384];
    __shared__ double wred[8];

    int tid  = threadIdx.x;
    int lane = tid & 31;
    int wid  = tid >> 5;

    int t = blockIdx.x;
    float ff = (float)NB + 0.5f;
    int bi = (int)(ff - sqrtf(ff*ff - 2.0f*t));
    if (bi < 0) bi = 0; if (bi >= NB) bi = NB-1;
    while (bi > 0 && tri_off(bi) > t) bi--;
    while (tri_off(bi+1) <= t) bi++;
    int bj = bi + (t - tri_off(bi));
    int rA = bi * 128, rB = bj * 128;

    int wm = (wid >> 2) * 64;
    int wn = (wid & 3)  * 32;

    float acc[4][4][4];
#pragma unroll
    for (int a = 0; a < 4; a++)
#pragma unroll
        for (int bq = 0; bq < 4; bq++)
#pragma unroll
            for (int c = 0; c < 4; c++) acc[a][bq][c] = 0.f;

    const char* xbytes = (const char*)g_xcat8;   // 256 B per row

    int r0 = tid >> 3;
    int cb = (tid & 7) * 16;

#pragma unroll
    for (int c = 0; c < 2; c++) {
        uint32_t a0 = (uint32_t)__cvta_generic_to_shared(As[c]);
        uint32_t b0 = (uint32_t)__cvta_generic_to_shared(Bs[c]);
#pragma unroll
        for (int p = 0; p < 4; p++) {
            int row = r0 + p*32;
            int sw  = row*128 + (cb ^ ((row & 7) * 16));
            int ga = rA + row, gb = rB + row;
            cpa16(a0 + sw, xbytes + (size_t)min(ga, NN-1)*256 + c*128 + cb, ga < NN);
            cpa16(b0 + sw, xbytes + (size_t)min(gb, NN-1)*256 + c*128 + cb, gb < NN);
        }
        asm volatile("cp.async.commit_group;\n");
    }

#pragma unroll
    for (int c = 0; c < 2; c++) {
        if (c == 0) asm volatile("cp.async.wait_group 1;\n");
        else        asm volatile("cp.async.wait_group 0;\n");
        __syncthreads();
        const char* Ab = As[c];
        const char* Bb = Bs[c];
#pragma unroll
        for (int ks = 0; ks < 4; ks++) {
            uint32_t afr[4][4];
            uint32_t bfr[2][4];
            int cbk = ks*32 + (lane >> 4)*16;
#pragma unroll
            for (int mb = 0; mb < 4; mb++) {
                int row = wm + mb*16 + (lane & 15);
                uint32_t sa = (uint32_t)__cvta_generic_to_shared(
                                  Ab + row*128 + (cbk ^ ((row & 7) * 16)));
                asm volatile("ldmatrix.sync.aligned.m8n8.x4.shared.b16 {%0,%1,%2,%3}, [%4];"
                    : "=r"(afr[mb][0]), "=r"(afr[mb][1]), "=r"(afr[mb][2]), "=r"(afr[mb][3])
                    : "r"(sa));
            }
#pragma unroll
            for (int nb2 = 0; nb2 < 2; nb2++) {
                int row = wn + nb2*16 + (lane & 15);
                uint32_t sb = (uint32_t)__cvta_generic_to_shared(
                                  Bb + row*128 + (cbk ^ ((row & 7) * 16)));
                asm volatile("ldmatrix.sync.aligned.m8n8.x4.shared.b16 {%0,%1,%2,%3}, [%4];"
                    : "=r"(bfr[nb2][0]), "=r"(bfr[nb2][1]), "=r"(bfr[nb2][2]), "=r"(bfr[nb2][3])
                    : "r"(sb));
            }
#pragma unroll
            for (int mb = 0; mb < 4; mb++)
#pragma unroll
                for (int nb = 0; nb < 4; nb++) {
                    int h = nb >> 1, o = nb & 1;
                    asm volatile(
                        "mma.sync.aligned.m16n8k32.row.col.f32.e4m3.e4m3.f32 "
                        "{%0,%1,%2,%3}, {%4,%5,%6,%7}, {%8,%9}, {%0,%1,%2,%3};"
                        : "+f"(acc[mb][nb][0]), "+f"(acc[mb][nb][1]),
                          "+f"(acc[mb][nb][2]), "+f"(acc[mb][nb][3])
                        : "r"(afr[mb][0]), "r"(afr[mb][1]), "r"(afr[mb][2]), "r"(afr[mb][3]),
                          "r"(bfr[h][o]),  "r"(bfr[h][o+2]));
                }
        }
        __syncthreads();
    }

    // epilogue: screen at 0.78 (covers worst-case e4m3 dot error),
    // exact fp32 recompute for rare candidates; neg_s from precomputed table.
    float lsum = 0.f;
#pragma unroll
    for (int mb = 0; mb < 4; mb++) {
        int rr0 = rA + wm + mb*16 + (lane >> 2);
#pragma unroll
        for (int nb = 0; nb < 4; nb++) {
            int c0 = rB + wn + nb*8 + (lane & 3)*2;
#pragma unroll
            for (int e = 0; e < 4; e++) {
                int gi = rr0 + (e >= 2 ? 8 : 0);
                int gj = c0 + (e & 1);
                float s = acc[mb][nb][e];
                if (gj > gi && gj < NN && gi < NN && s > 0.78f) {
                    const float4* av = (const float4*)(xall + (size_t)gi*DALL);
                    const float4* bv = (const float4*)(xall + (size_t)gj*DALL);
                    float d = 0.f;
#pragma unroll 4
                    for (int q = 0; q < 64; q++) {
                        float4 x = av[q], y = bv[q];
                        d += x.x*y.x + x.y*y.y + x.z*y.z + x.w*y.w;
                    }
                    float se = 0.5f * d;
                    if (se > 0.95f) {
                        float u = (se - 0.1f) * (1.0f/0.9f);
                        lsum += (u*u) * log1pf(expf(g_negs[gi] - se));
                    }
                }
            }
        }
    }
    float v = lsum;
#pragma unroll
    for (int o = 16; o; o >>= 1) v += __shfl_xor_sync(0xffffffffu, v, o);
    if (lane == 0) wred[wid] = (double)v;
    __syncthreads();
    if (tid == 0) {
        double s = 0;
#pragma unroll
        for (int q = 0; q < 8; q++) s += wred[q];
        if (s != 0.0) atomicAdd(&g_acc[1], s);
    }
}

// ---------------- finalize + re-zero scratch for next replay ------------------
__global__ void k_final(float* out, int loss_idx) {
    int i = blockIdx.x*blockDim.x + threadIdx.x;
    if (i == 0) {
        double lc   = -g_acc[2] / (double)PP;
        double loss = g_acc[0] + g_acc[1] + 1.0 * lc;   // LAMBDA1 = 1
        out[loss_idx] = (float)loss;
        g_acc[0] = 0.0; g_acc[1] = 0.0; g_acc[2] = 0.0;
    }
    if (i < 2*(NN+1)) ((int*)g_off)[i] = 0;
}

// --------- launch (forked: sup ∥ CSR chain, then gather ∥ pseudo) --------------
extern "C" void kernel_launch(void* const* d_in, const int* in_sizes, int n_in,
                              void* d_out, int out_size) {
    const float* x0  = (const float*)d_in[0];
    const float* x1  = (const float*)d_in[1];
    const int*   a0s = (const int*)d_in[2];
    const int*   a0d = (const int*)d_in[3];
    const float* a0v = (const float*)d_in[4];
    const int*   a1s = (const int*)d_in[5];
    const int*   a1d = (const int*)d_in[6];
    const float* a1v = (const float*)d_in[7];
    const int*   ts  = (const int*)d_in[8];
    const int*   ngi = (const int*)d_in[9];
    const int*   ngr = (const int*)d_in[10];
    const int*   na  = (const int*)d_in[11];
    const int*   nb  = (const int*)d_in[12];
    const int*   nl  = (const int*)d_in[13];
    const float* W0  = (const float*)d_in[14];
    const float* b0  = (const float*)d_in[15];
    const float* W1  = (const float*)d_in[16];
    const float* b1  = (const float*)d_in[17];
    float* out = (float*)d_out;

    // created once on the (uncaptured) correctness call; reused by capture
    static cudaStream_t s2 = nullptr;
    static cudaEvent_t  evF = nullptr, evS = nullptr, evJ = nullptr;
    if (s2 == nullptr) {
        cudaStreamCreateWithFlags(&s2, cudaStreamNonBlocking);
        cudaEventCreateWithFlags(&evF, cudaEventDisableTiming);
        cudaEventCreateWithFlags(&evS, cudaEventDisableTiming);
        cudaEventCreateWithFlags(&evJ, cudaEventDisableTiming);
    }

    k_front<<<FRONT_B, 256>>>(a0d, a1d, x0, x1, W0, W1);

    // fork 1: sup GEMM (needs prep only) ∥ CSR scan+fill (needs counts only)
    cudaEventRecord(evF, 0);
    cudaStreamWaitEvent(s2, evF, 0);
    k_sup  <<<dim3(NB,1,2), 256, 0, s2>>>(b0, b1);
    cudaEventRecord(evS, s2);

    k_scan <<<1, 512>>>();
    k_fill <<<CNT_B, 256>>>(a0s, a0d, a0v, a1s, a1d, a1v);
    cudaStreamWaitEvent(0, evS, 0);

    k_agg  <<<dim3(NN,2), 128>>>(out);
    k_negs <<<GN_B, 256>>>(ngr);

    // fork 2: pseudo screen-GEMM ∥ pair gathers
    cudaEventRecord(evF, 0);
    cudaStreamWaitEvent(s2, evF, 0);
    k_pseudo<<<NTILES, 256, 0, s2>>>(out);
    cudaEventRecord(evJ, s2);

    k_gather<<<GATHER_B, 256>>>(ts, ngi, na, nb, nl);
    cudaStreamWaitEvent(0, evJ, 0);
    k_final <<<(2*(NN+1)+255)/256, 256>>>(out, out_size - 1);
}

// round 16
// speedup vs baseline: 2.2760x; 1.1885x over previous
#include <cuda_runtime.h>
#include <cuda_bf16.h>
#include <cuda_fp8.h>
#include <cstdint>
#include <math.h>

#define NN   10000
#define EE   320000
#define DIN  256
#define HIDN 128
#define DALL 256
#define MM   100000
#define PP   15000
#define NB   79                    // ceil(NN/128)
#define NTILES ((NB*(NB+1))/2)     // 3160 upper-tri tiles
#define K3   768                   // 3-term bf16 split K for sup GEMM
#define PREP_T   (2*NN*32 + 2*DIN*HIDN)      // 705536 prep threads
#define PREP_B   ((PREP_T + 255)/256)        // 2756
#define CNT_B    (2*EE/256)                  // 2500
#define FRONT_B  (CNT_B + PREP_B)
#define GR_B     (MM/32)                     // 3125 real blocks (32 pairs each)
#define GL_B     ((PP+31)/32)                // 469 lc blocks
#define GN_B     ((NN+31)/32)                // 313 negs blocks
#define GATHER_B (GR_B + GL_B)

// ---------------- static device scratch (no allocations allowed) ------------
__device__ float  g_sup[2][NN*HIDN];
__device__ int    g_off[2][NN+1];        // zero-init by loader; re-zeroed by k_final
__device__ int    g_cur[2][NN];
__device__ int2   g_edge[2][EE];         // {src*512 (byte off), val bits}
__device__ float  g_negs[NN];
__device__ double g_acc[3];              // [0]=real [1]=pseudo [2]=lc ; re-zeroed by k_final
__device__ __align__(16) unsigned char  g_xcat8[NN*128];   // e4m3 xn FIRST HALF, 1.28 MB
__device__ __align__(16) __nv_bfloat16  g_xnb[NN*DALL];    // bf16 xn, 5.12 MB
__device__ __align__(16) __nv_bfloat16  g_x3[2*NN*K3];     // (xh,xl,xh) triples
__device__ __align__(16) __nv_bfloat16  g_w3[2*HIDN*K3];   // (Wh,Wh,Wl) triples

// ---------------- helpers ----------------------------------------------------
__device__ __forceinline__ int tri_off(int b) { return b*NB - (b*(b-1))/2; }

__device__ __forceinline__ void cpa16(uint32_t smem_dst, const void* gsrc, int valid) {
    asm volatile("cp.async.cg.shared.global [%0], [%1], 16, %2;\n"
                 :: "r"(smem_dst), "l"(gsrc), "r"(valid ? 16 : 0));
}

__device__ __forceinline__ float dot8bf(uint4 a, uint4 b) {
    const __nv_bfloat162* pa = (const __nv_bfloat162*)&a;
    const __nv_bfloat162* pb = (const __nv_bfloat162*)&b;
    float s = 0.f;
#pragma unroll
    for (int i = 0; i < 4; i++) {
        float2 fa = __bfloat1622float2(pa[i]);
        float2 fb = __bfloat1622float2(pb[i]);
        s = fmaf(fa.x, fb.x, s);
        s = fmaf(fa.y, fb.y, s);
    }
    return s;
}

// ================= FRONT: edge counting ∥ bf16 split prep =====================
__global__ __launch_bounds__(256)
void k_front(const int* __restrict__ d0, const int* __restrict__ d1,
             const float* __restrict__ x0, const float* __restrict__ x1,
             const float* __restrict__ W0, const float* __restrict__ W1) {
    int b = blockIdx.x;
    if (b < CNT_B) {
        int i = b*256 + threadIdx.x;
        if (i < EE)            atomicAdd(&g_off[0][d0[i]+1], 1);
        else if (i < 2*EE)     atomicAdd(&g_off[1][d1[i-EE]+1], 1);
        return;
    }
    int i = (b - CNT_B)*256 + threadIdx.x;
    if (i < 2*NN*32) {
        int g   = i / (NN*32);
        int rr  = i % (NN*32);
        int n   = rr >> 5;
        int k0  = (rr & 31) * 8;
        const float* src = (g ? x1 : x0) + (size_t)n*DIN + k0;
        float4 v0 = *(const float4*)(src);
        float4 v1 = *(const float4*)(src + 4);
        float xv[8] = {v0.x,v0.y,v0.z,v0.w,v1.x,v1.y,v1.z,v1.w};
        __nv_bfloat16 o[24];
#pragma unroll
        for (int j = 0; j < 8; j++) {
            __nv_bfloat16 h = __float2bfloat16_rn(xv[j]);
            __nv_bfloat16 l = __float2bfloat16_rn(xv[j] - __bfloat162float(h));
            o[3*j] = h; o[3*j+1] = l; o[3*j+2] = h;
        }
        __nv_bfloat16* dst = g_x3 + ((size_t)g*NN + n)*K3 + k0*3;
        ((uint4*)dst)[0] = ((uint4*)o)[0];
        ((uint4*)dst)[1] = ((uint4*)o)[1];
        ((uint4*)dst)[2] = ((uint4*)o)[2];
    } else if (i < PREP_T) {
        int j = i - 2*NN*32;
        int g = j >> 15;
        int rem = j & 32767;
        int k = rem >> 7;
        int n = rem & 127;
        float wv = (g ? W1 : W0)[(size_t)k*HIDN + n];
        __nv_bfloat16 h = __float2bfloat16_rn(wv);
        __nv_bfloat16 l = __float2bfloat16_rn(wv - __bfloat162float(h));
        size_t wb = ((size_t)g*HIDN + n)*K3 + 3*k;
        g_w3[wb] = h; g_w3[wb+1] = h; g_w3[wb+2] = l;
    }
}

// ---------------- CSR build: parallel scan (1 block, 512 threads) ------------
__global__ void k_scan() {
    __shared__ int wsum[17];
    int tid = threadIdx.x, lane = tid & 31, w = tid >> 5;
    const int TOT = NN+1;
    const int CH  = (TOT + 511)/512;   // 20
    for (int g = 0; g < 2; g++) {
        int s = tid*CH, e = min(s+CH, TOT);
        int sum = 0;
        for (int i = s; i < e; i++) sum += g_off[g][i];
        int v = sum;
#pragma unroll
        for (int o = 1; o < 32; o <<= 1) {
            int t = __shfl_up_sync(0xffffffffu, v, o);
            if (lane >= o) v += t;
        }
        if (lane == 31) wsum[w+1] = v;
        __syncthreads();
        if (w == 0) {
            int x = (lane < 16) ? wsum[lane+1] : 0;
#pragma unroll
            for (int o = 1; o < 16; o <<= 1) {
                int t = __shfl_up_sync(0xffffffffu, x, o);
                if (lane >= o) x += t;
            }
            if (lane < 16) wsum[lane+1] = x;
            if (lane == 0) wsum[0] = 0;
        }
        __syncthreads();
        int run = v - sum + wsum[w];
        for (int i = s; i < e; i++) {
            run += g_off[g][i];
            g_off[g][i] = run;
            if (i < NN) g_cur[g][i] = run;
        }
        __syncthreads();
    }
}

// ---------------- CSR fill (edge records) -------------------------------------
__global__ __launch_bounds__(256)
void k_fill(const int* __restrict__ s0, const int* __restrict__ d0,
            const float* __restrict__ v0,
            const int* __restrict__ s1, const int* __restrict__ d1,
            const float* __restrict__ v1) {
    int i = blockIdx.x*256 + threadIdx.x;
    if (i < EE) {
        int p = atomicAdd(&g_cur[0][d0[i]], 1);
        g_edge[0][p] = make_int2(s0[i]*512, __float_as_int(v0[i]));
    } else if (i < 2*EE) {
        int j = i - EE;
        int p = atomicAdd(&g_cur[1][d1[j]], 1);
        g_edge[1][p] = make_int2(s1[j]*512, __float_as_int(v1[j]));
    }
}

// ---------------- sup = x @ W + b (bf16 mma, 3-term split, K=768) -------------
__global__ __launch_bounds__(256)
void k_sup(const float* __restrict__ b0, const float* __restrict__ b1) {
    __shared__ __align__(16) char As[16384];
    __shared__ __align__(16) char Bs[16384];

    int g   = blockIdx.z;
    int rb  = blockIdx.x * 128;
    int tid = threadIdx.x;
    int lane = tid & 31;
    int wid  = tid >> 5;
    int wm   = (wid >> 2) * 64;
    int wn   = (wid & 3)  * 32;

    const float* bias = g ? b1 : b0;
    float* sup = g_sup[g];

    float acc[4][4][4];
#pragma unroll
    for (int a = 0; a < 4; a++)
#pragma unroll
        for (int bq = 0; bq < 4; bq++)
#pragma unroll
            for (int c = 0; c < 4; c++) acc[a][bq][c] = 0.f;

    const char* xb = (const char*)(g_x3 + (size_t)g*NN*K3);
    const char* wb = (const char*)(g_w3 + (size_t)g*HIDN*K3);

    for (int kc = 0; kc < 12; kc++) {
#pragma unroll
        for (int p = 0; p < 4; p++) {
            int idx = p*256 + tid;
            int row = idx >> 3;
            int cb  = (idx & 7) * 16;
            int sw  = row*128 + (cb ^ ((row & 7) * 16));
            int ga  = rb + row;
            uint4 va = make_uint4(0u,0u,0u,0u);
            if (ga < NN) va = *(const uint4*)(xb + (size_t)ga*1536 + kc*128 + cb);
            uint4 vb = *(const uint4*)(wb + (size_t)row*1536 + kc*128 + cb);
            *(uint4*)(As + sw) = va;
            *(uint4*)(Bs + sw) = vb;
        }
        __syncthreads();
#pragma unroll
        for (int ks = 0; ks < 4; ks++) {
            uint32_t afr[4][4];
            uint32_t bfr[2][4];
            int cbk = ks*32 + (lane >> 4)*16;
#pragma unroll
            for (int mb = 0; mb < 4; mb++) {
                int row = wm + mb*16 + (lane & 15);
                uint32_t sa = (uint32_t)__cvta_generic_to_shared(
                                  As + row*128 + (cbk ^ ((row & 7) * 16)));
                asm volatile("ldmatrix.sync.aligned.m8n8.x4.shared.b16 {%0,%1,%2,%3}, [%4];"
                    : "=r"(afr[mb][0]), "=r"(afr[mb][1]), "=r"(afr[mb][2]), "=r"(afr[mb][3])
                    : "r"(sa));
            }
#pragma unroll
            for (int nb2 = 0; nb2 < 2; nb2++) {
                int row = wn + nb2*16 + (lane & 15);
                uint32_t sb = (uint32_t)__cvta_generic_to_shared(
                                  Bs + row*128 + (cbk ^ ((row & 7) * 16)));
                asm volatile("ldmatrix.sync.aligned.m8n8.x4.shared.b16 {%0,%1,%2,%3}, [%4];"
                    : "=r"(bfr[nb2][0]), "=r"(bfr[nb2][1]), "=r"(bfr[nb2][2]), "=r"(bfr[nb2][3])
                    : "r"(sb));
            }
#pragma unroll
            for (int mb = 0; mb < 4; mb++)
#pragma unroll
                for (int nb = 0; nb < 4; nb++) {
                    int h = nb >> 1, o = nb & 1;
                    asm volatile(
                        "mma.sync.aligned.m16n8k16.row.col.f32.bf16.bf16.f32 "
                        "{%0,%1,%2,%3}, {%4,%5,%6,%7}, {%8,%9}, {%0,%1,%2,%3};"
                        : "+f"(acc[mb][nb][0]), "+f"(acc[mb][nb][1]),
                          "+f"(acc[mb][nb][2]), "+f"(acc[mb][nb][3])
                        : "r"(afr[mb][0]), "r"(afr[mb][1]), "r"(afr[mb][2]), "r"(afr[mb][3]),
                          "r"(bfr[h][o]),  "r"(bfr[h][o+2]));
                }
        }
        __syncthreads();
    }

#pragma unroll
    for (int nb = 0; nb < 4; nb++) {
        int col = wn + nb*8 + (lane & 3)*2;
        float bc0 = bias[col], bc1 = bias[col+1];
#pragma unroll
        for (int mb = 0; mb < 4; mb++) {
            int r = wm + mb*16 + (lane >> 2);
            int gr0 = rb + r, gr1 = rb + r + 8;
            if (gr0 < NN) {
                float2 o = make_float2(acc[mb][nb][0] + bc0, acc[mb][nb][1] + bc1);
                *(float2*)(sup + (size_t)gr0*HIDN + col) = o;
            }
            if (gr1 < NN) {
                float2 o = make_float2(acc[mb][nb][2] + bc0, acc[mb][nb][3] + bc1);
                *(float2*)(sup + (size_t)gr1*HIDN + col) = o;
            }
        }
    }
}

// ------- aggregate + l2norm -> x_all + fused fp8/bf16 casts (warp-per-edge) ---
__global__ __launch_bounds__(128)
void k_agg(float* __restrict__ out) {
    int n   = blockIdx.x;
    int g   = blockIdx.y;
    int tid = threadIdx.x;
    int lane = tid & 31;
    int w    = tid >> 5;
    const char* supb = (const char*)g_sup[g] + lane*16;

    float4 a4 = make_float4(0.f, 0.f, 0.f, 0.f);
    int s0 = g_off[g][n], s1 = g_off[g][n+1];
    const int2* edges = g_edge[g];
#pragma unroll 4
    for (int e = s0 + w; e < s1; e += 4) {
        int2 rec = edges[e];
        float4 v = *(const float4*)(supb + rec.x);
        float val = __int_as_float(rec.y);
        a4.x = fmaf(v.x, val, a4.x);
        a4.y = fmaf(v.y, val, a4.y);
        a4.z = fmaf(v.z, val, a4.z);
        a4.w = fmaf(v.w, val, a4.w);
    }
    __shared__ float part[4][128];
    *(float4*)&part[w][lane*4] = a4;
    __syncthreads();
    float acc = part[0][tid] + part[1][tid] + part[2][tid] + part[3][tid];

    float sq = acc*acc;
#pragma unroll
    for (int o = 16; o; o >>= 1) sq += __shfl_xor_sync(0xffffffffu, sq, o);
    __shared__ float wsum[4];
    if (lane == 0) wsum[w] = sq;
    __syncthreads();
    float tot = wsum[0] + wsum[1] + wsum[2] + wsum[3];
    float v = acc / sqrtf(tot);
    out[(size_t)n*DALL + g*HIDN + tid] = v;

    float xs = v * 0.70710678118654752440f;
    if (g == 0)   // screening operand: first half only (h0/sqrt(2))
        g_xcat8[(size_t)n*128 + tid] =
            __nv_cvt_float_to_fp8(xs, __NV_SATFINITE, __NV_E4M3);
    g_xnb[(size_t)n*DALL + g*128 + tid] = __float2bfloat16_rn(xs);
}

// ---------------- neg_s precompute (bf16, lean) --------------------------------
__global__ __launch_bounds__(256)
void k_negs(const int* __restrict__ negrow) {
    int lane = threadIdx.x & 31;
    int wid  = threadIdx.x >> 5;
#pragma unroll
    for (int pq = 0; pq < 4; pq++) {
        int row = blockIdx.x*32 + wid*4 + pq;
        if (row >= NN) break;
        int jn = negrow[row];
        uint4 a = ((const uint4*)(g_xnb + (size_t)row*DALL))[lane];
        uint4 b = ((const uint4*)(g_xnb + (size_t)jn*DALL))[lane];
        float s = dot8bf(a, b);
#pragma unroll
        for (int o = 16; o; o >>= 1) s += __shfl_xor_sync(0xffffffffu, s, o);
        if (lane == 0) g_negs[row] = s;   // bf16 xn rows are unit-norm
    }
}

// ========== GATHER: loss_real + lc (bf16 rows, high occupancy) ================
__global__ __launch_bounds__(256)
void k_gather(const int* __restrict__ ts, const int* __restrict__ negidx,
              const int* __restrict__ na, const int* __restrict__ nbv,
              const int* __restrict__ nl) {
    __shared__ float wr[8];
    int b    = blockIdx.x;
    int tid  = threadIdx.x;
    int lane = tid & 31;
    int wid  = tid >> 5;

    if (b < GR_B) {
        // -------- REAL role: 32 pairs/block, 4 per warp --------
        float term = 0.f;
#pragma unroll
        for (int pq = 0; pq < 4; pq++) {
            int pid = b*32 + wid*4 + pq;
            int t0 = ts[2*pid], t1 = ts[2*pid+1], tn = negidx[pid];
            uint4 r = ((const uint4*)(g_xnb + (size_t)t0*DALL))[lane];
            uint4 e = ((const uint4*)(g_xnb + (size_t)t1*DALL))[lane];
            uint4 n = ((const uint4*)(g_xnb + (size_t)tn*DALL))[lane];
            float ps = dot8bf(r, e);
            float ns = dot8bf(r, n);
#pragma unroll
            for (int o = 16; o; o >>= 1) {
                ps += __shfl_xor_sync(0xffffffffu, ps, o);
                ns += __shfl_xor_sync(0xffffffffu, ns, o);
            }
            if (lane == 0) {
                float u = (ps - 0.1f) * (1.0f/0.9f);
                term += (u*u) * log1pf(expf(ns - ps));
            }
        }
        if (lane == 0) wr[wid] = term;
        __syncthreads();
        if (tid == 0) {
            double s = 0;
#pragma unroll
            for (int q = 0; q < 8; q++) s += (double)wr[q];
            atomicAdd(&g_acc[0], s);
        }
    } else {
        // -------- LC role: 32 pairs/block, 4 per warp --------
        int b2 = b - GR_B;
        float term = 0.f;
#pragma unroll
        for (int pq = 0; pq < 4; pq++) {
            int pid = b2*32 + wid*4 + pq;
            if (pid >= PP) break;
            int ia = na[pid], ib = nbv[pid];
            uint4 a  = ((const uint4*)(g_xnb + (size_t)ia*DALL))[lane];
            uint4 bb = ((const uint4*)(g_xnb + (size_t)ib*DALL))[lane];
            float s = dot8bf(a, bb);
#pragma unroll
            for (int o = 16; o; o >>= 1) s += __shfl_xor_sync(0xffffffffu, s, o);
            if (lane == 0) {
                float z   = s * 2.0f;                 // sim / TAU0
                float ls  = (z >= 0.f) ? -log1pf(expf(-z)) : (z - log1pf(expf(z)));
                int   L   = nl[pid];
                term += ldexpf(1.0f, -(L+1)) * ls;    // 0.5^(L+1)
            }
        }
        if (lane == 0) wr[wid] = term;
        __syncthreads();
        if (tid == 0) {
            double s = 0;
#pragma unroll
            for (int q = 0; q < 8; q++) s += (double)wr[q];
            atomicAdd(&g_acc[2], s);
        }
    }
}

// ====== PSEUDO: fp8 K=128 half-screen GEMM over triu tiles ====================
// sim = s_half0 + s_half1, s_half1 <= 0.5 exactly (halves have norm 1/sqrt 2),
// so sim > 0.95 ==> s_half0 > 0.45. Screen fp8 s_half0 at 0.35 (covers fp8
// error <= ~0.07); exact fp32 full recompute decides the true 0.95 mask.
__global__ __launch_bounds__(256, 2)
void k_pseudo(const float* __restrict__ xall) {
    __shared__ __align__(128) char As[16384];
    __shared__ __align__(128) char Bs[16384];
    __shared__ double wred[8];

    int tid  = threadIdx.x;
    int lane = tid & 31;
    int wid  = tid >> 5;

    int t = blockIdx.x;
    float ff = (float)NB + 0.5f;
    int bi = (int)(ff - sqrtf(ff*ff - 2.0f*t));
    if (bi < 0) bi = 0; if (bi >= NB) bi = NB-1;
    while (bi > 0 && tri_off(bi) > t) bi--;
    while (tri_off(bi+1) <= t) bi++;
    int bj = bi + (t - tri_off(bi));
    int rA = bi * 128, rB = bj * 128;

    int wm = (wid >> 2) * 64;
    int wn = (wid & 3)  * 32;

    float acc[4][4][4];
#pragma unroll
    for (int a = 0; a < 4; a++)
#pragma unroll
        for (int bq = 0; bq < 4; bq++)
#pragma unroll
            for (int c = 0; c < 4; c++) acc[a][bq][c] = 0.f;

    const char* xbytes = (const char*)g_xcat8;   // 128 B per row (first half)

    int r0 = tid >> 3;
    int cb = (tid & 7) * 16;

    {
        uint32_t a0 = (uint32_t)__cvta_generic_to_shared(As);
        uint32_t b0 = (uint32_t)__cvta_generic_to_shared(Bs);
#pragma unroll
        for (int p = 0; p < 4; p++) {
            int row = r0 + p*32;
            int sw  = row*128 + (cb ^ ((row & 7) * 16));
            int ga = rA + row, gb = rB + row;
            cpa16(a0 + sw, xbytes + (size_t)min(ga, NN-1)*128 + cb, ga < NN);
            cpa16(b0 + sw, xbytes + (size_t)min(gb, NN-1)*128 + cb, gb < NN);
        }
        asm volatile("cp.async.commit_group;\n");
        asm volatile("cp.async.wait_group 0;\n");
    }
    __syncthreads();

#pragma unroll
    for (int ks = 0; ks < 4; ks++) {      // 4 x k32 steps (K=128)
        uint32_t afr[4][4];
        uint32_t bfr[2][4];
        int cbk = ks*32 + (lane >> 4)*16;
#pragma unroll
        for (int mb = 0; mb < 4; mb++) {
            int row = wm + mb*16 + (lane & 15);
            uint32_t sa = (uint32_t)__cvta_generic_to_shared(
                              As + row*128 + (cbk ^ ((row & 7) * 16)));
            asm volatile("ldmatrix.sync.aligned.m8n8.x4.shared.b16 {%0,%1,%2,%3}, [%4];"
                : "=r"(afr[mb][0]), "=r"(afr[mb][1]), "=r"(afr[mb][2]), "=r"(afr[mb][3])
                : "r"(sa));
        }
#pragma unroll
        for (int nb2 = 0; nb2 < 2; nb2++) {
            int row = wn + nb2*16 + (lane & 15);
            uint32_t sb = (uint32_t)__cvta_generic_to_shared(
                              Bs + row*128 + (cbk ^ ((row & 7) * 16)));
            asm volatile("ldmatrix.sync.aligned.m8n8.x4.shared.b16 {%0,%1,%2,%3}, [%4];"
                : "=r"(bfr[nb2][0]), "=r"(bfr[nb2][1]), "=r"(bfr[nb2][2]), "=r"(bfr[nb2][3])
                : "r"(sb));
        }
#pragma unroll
        for (int mb = 0; mb < 4; mb++)
#pragma unroll
            for (int nb = 0; nb < 4; nb++) {
                int h = nb >> 1, o = nb & 1;
                asm volatile(
                    "mma.sync.aligned.m16n8k32.row.col.f32.e4m3.e4m3.f32 "
                    "{%0,%1,%2,%3}, {%4,%5,%6,%7}, {%8,%9}, {%0,%1,%2,%3};"
                    : "+f"(acc[mb][nb][0]), "+f"(acc[mb][nb][1]),
                      "+f"(acc[mb][nb][2]), "+f"(acc[mb][nb][3])
                    : "r"(afr[mb][0]), "r"(afr[mb][1]), "r"(afr[mb][2]), "r"(afr[mb][3]),
                      "r"(bfr[h][o]),  "r"(bfr[h][o+2]));
            }
    }
    __syncthreads();

    // epilogue: half-screen at 0.35; exact fp32 full recompute for candidates.
    float lsum = 0.f;
#pragma unroll
    for (int mb = 0; mb < 4; mb++) {
        int rr0 = rA + wm + mb*16 + (lane >> 2);
#pragma unroll
        for (int nb = 0; nb < 4; nb++) {
            int c0 = rB + wn + nb*8 + (lane & 3)*2;
#pragma unroll
            for (int e = 0; e < 4; e++) {
                int gi = rr0 + (e >= 2 ? 8 : 0);
                int gj = c0 + (e & 1);
                float s = acc[mb][nb][e];
                if (gj > gi && gj < NN && gi < NN && s > 0.35f) {
                    const float4* av = (const float4*)(xall + (size_t)gi*DALL);
                    const float4* bv = (const float4*)(xall + (size_t)gj*DALL);
                    float d = 0.f;
#pragma unroll 4
                    for (int q = 0; q < 64; q++) {
                        float4 x = av[q], y = bv[q];
                        d += x.x*y.x + x.y*y.y + x.z*y.z + x.w*y.w;
                    }
                    float se = 0.5f * d;
                    if (se > 0.95f) {
                        float u = (se - 0.1f) * (1.0f/0.9f);
                        lsum += (u*u) * log1pf(expf(g_negs[gi] - se));
                    }
                }
            }
        }
    }
    float v = lsum;
#pragma unroll
    for (int o = 16; o; o >>= 1) v += __shfl_xor_sync(0xffffffffu, v, o);
    if (lane == 0) wred[wid] = (double)v;
    __syncthreads();
    if (tid == 0) {
        double s = 0;
#pragma unroll
        for (int q = 0; q < 8; q++) s += wred[q];
        if (s != 0.0) atomicAdd(&g_acc[1], s);
    }
}

// ---------------- finalize + re-zero scratch for next replay ------------------
__global__ void k_final(float* out, int loss_idx) {
    int i = blockIdx.x*blockDim.x + threadIdx.x;
    if (i == 0) {
        double lc   = -g_acc[2] / (double)PP;
        double loss = g_acc[0] + g_acc[1] + 1.0 * lc;   // LAMBDA1 = 1
        out[loss_idx] = (float)loss;
        g_acc[0] = 0.0; g_acc[1] = 0.0; g_acc[2] = 0.0;
    }
    if (i < 2*(NN+1)) ((int*)g_off)[i] = 0;
}

// --------- launch (forked: sup ∥ CSR chain, then gather ∥ pseudo) --------------
extern "C" void kernel_launch(void* const* d_in, const int* in_sizes, int n_in,
                              void* d_out, int out_size) {
    const float* x0  = (const float*)d_in[0];
    const float* x1  = (const float*)d_in[1];
    const int*   a0s = (const int*)d_in[2];
    const int*   a0d = (const int*)d_in[3];
    const float* a0v = (const float*)d_in[4];
    const int*   a1s = (const int*)d_in[5];
    const int*   a1d = (const int*)d_in[6];
    const float* a1v = (const float*)d_in[7];
    const int*   ts  = (const int*)d_in[8];
    const int*   ngi = (const int*)d_in[9];
    const int*   ngr = (const int*)d_in[10];
    const int*   na  = (const int*)d_in[11];
    const int*   nb  = (const int*)d_in[12];
    const int*   nl  = (const int*)d_in[13];
    const float* W0  = (const float*)d_in[14];
    const float* b0  = (const float*)d_in[15];
    const float* W1  = (const float*)d_in[16];
    const float* b1  = (const float*)d_in[17];
    float* out = (float*)d_out;

    // created once on the (uncaptured) correctness call; reused by capture
    static cudaStream_t s2 = nullptr;
    static cudaEvent_t  evF = nullptr, evS = nullptr, evJ = nullptr;
    if (s2 == nullptr) {
        cudaStreamCreateWithFlags(&s2, cudaStreamNonBlocking);
        cudaEventCreateWithFlags(&evF, cudaEventDisableTiming);
        cudaEventCreateWithFlags(&evS, cudaEventDisableTiming);
        cudaEventCreateWithFlags(&evJ, cudaEventDisableTiming);
    }

    k_front<<<FRONT_B, 256>>>(a0d, a1d, x0, x1, W0, W1);

    // fork 1: sup GEMM (needs prep only) ∥ CSR scan+fill (needs counts only)
    cudaEventRecord(evF, 0);
    cudaStreamWaitEvent(s2, evF, 0);
    k_sup  <<<dim3(NB,1,2), 256, 0, s2>>>(b0, b1);
    cudaEventRecord(evS, s2);

    k_scan <<<1, 512>>>();
    k_fill <<<CNT_B, 256>>>(a0s, a0d, a0v, a1s, a1d, a1v);
    cudaStreamWaitEvent(0, evS, 0);

    k_agg  <<<dim3(NN,2), 128>>>(out);
    k_negs <<<GN_B, 256>>>(ngr);

    // fork 2: pseudo half-screen GEMM ∥ pair gathers
    cudaEventRecord(evF, 0);
    cudaStreamWaitEvent(s2, evF, 0);
    k_pseudo<<<NTILES, 256, 0, s2>>>(out);
    cudaEventRecord(evJ, s2);

    k_gather<<<GATHER_B, 256>>>(ts, ngi, na, nb, nl);
    cudaStreamWaitEvent(0, evJ, 0);
    k_final <<<(2*(NN+1)+255)/256, 256>>>(out, out_size - 1);
}